// round 17
// baseline (speedup 1.0000x reference)
#include <cuda_runtime.h>
#include <cstdint>

// ItemCodeDPQ: out[b,s,m*16+d] = centroids[m, clamp(item_codes[input_ids[b,s], m],0,255), d]
//              zeroed where input_ids[b,s] == 0.  input_ids arrive as int32.
//
// R17 = R6 exactly, except stores use the DEFAULT (write-back, evict-normal)
// policy instead of __stcs. Rationale: the 105MB output fits in the 126MB L2;
// under graph-replay steady state a dirty line overwritten by the next replay
// never pays a DRAM write. __stcs was forcing the full 105MB to HBM per
// replay -- the suspected 21us plateau.

__global__ void __launch_bounds__(256)
itemcode_dpq_kernel(const int* __restrict__ input_ids,
                    const int* __restrict__ item_codes,
                    const float4* __restrict__ centroids4,
                    float4* __restrict__ out4,
                    int ntok)
{
    const unsigned lane = threadIdx.x & 31u;
    const unsigned sub  = lane >> 2;          // 0..7 : sub-codebook this lane serves
    const unsigned part = lane & 3u;          // 0..3 : float4 within 16-float sub-emb

    const unsigned warp = (blockIdx.x * blockDim.x + threadIdx.x) >> 5;
    const unsigned t0   = warp * 16u;
    if (t0 >= (unsigned)ntok) return;         // ntok = 204800 is divisible by 16

    #pragma unroll
    for (int j = 0; j < 16; j++) {
        const unsigned t = t0 + (unsigned)j;
        // uniform load: whole warp reads one word (16 of these share 1 line)
        const unsigned id = (unsigned)__ldg(&input_ids[t]);
        // per-lane code load: 8 distinct words per warp = one 32B sector
        int code = __ldg(&item_codes[id * 8u + sub]);
        code = min(max(code, 0), 255);

        float4 v;
        if (id == 0u) {
            v = make_float4(0.f, 0.f, 0.f, 0.f);
        } else {
            v = __ldg(&centroids4[(sub * 256u + (unsigned)code) * 4u + part]);
        }
        out4[t * 32u + lane] = v;             // default write-back store
    }
}

extern "C" void kernel_launch(void* const* d_in, const int* in_sizes, int n_in,
                              void* d_out, int out_size)
{
    const int*    input_ids  = (const int*)d_in[0];     // (1024,200) int32
    const int*    item_codes = (const int*)d_in[1];     // (1e6, 8) int32
    const float4* centroids  = (const float4*)d_in[2];  // (8,256,16) fp32
    float4*       out        = (float4*)d_out;          // (1024,200,128) fp32

    const int ntok = in_sizes[0];   // 204800

    // 16 tokens per warp, 8 warps per 256-thread CTA => 128 tokens per CTA
    int warps = (ntok + 15) / 16;
    int ctas  = (warps + 7) / 8;
    itemcode_dpq_kernel<<<ctas, 256>>>(input_ids, item_codes, centroids,
                                       out, ntok);
}